// round 2
// baseline (speedup 1.0000x reference)
#include <cuda_runtime.h>

// Problem constants (fixed by the reference shapes)
#define NB      32          // batch
#define NT      2048        // encoder time steps
#define HE      1024        // encoder hidden
#define DEC     2048        // flattened decoder hidden (2*1024)

#define SPLITS  16          // T-splits per batch
#define CHUNK   (NT / SPLITS)       // 128 rows per CTA
#define TILE    8                   // rows per SMEM tile (32 KB)
#define NTILES  (CHUNK / TILE)      // 16
#define THREADS 256

// Split partials: 32*16*1024 fp32 acc + m + l  (~2 MB, static device scratch)
__device__ float g_acc[NB * SPLITS * HE];
__device__ float g_m[NB * SPLITS];
__device__ float g_l[NB * SPLITS];

// ---------------------------------------------------------------------------
// Kernel 1: per-(batch, split) flash-style single-query attention partial.
//   weights_t = mask_t * exp(mask_t*(enc_t . w_e + h_b) - m)
//   acc[e]    = sum_t weights_t * enc[t][e],   l = sum_t weights_t
// ---------------------------------------------------------------------------
__global__ __launch_bounds__(THREADS) void attn_partial_kernel(
    const float* __restrict__ hidden,   // (2, 32, 1024)
    const float* __restrict__ enc,      // (32, 2048, 1024)
    const float* __restrict__ mask,     // (32, 2048)
    const float* __restrict__ attn_w,   // (3072,)
    const float* __restrict__ attn_b)   // (1,)
{
    __shared__ float4 tile[TILE * HE / 4];   // 32 KB staging tile
    __shared__ float  we_sh[HE];             // 4 KB: w_e
    __shared__ float  e_sh[TILE], mask_sh[TILE], f_sh[TILE];
    __shared__ float  scale_sh, m_sh, l_sh, hb_sh;
    __shared__ float  red[THREADS];

    const int tid  = threadIdx.x;
    const int lane = tid & 31;
    const int wid  = tid >> 5;
    const int b    = blockIdx.y;     // batch
    const int s    = blockIdx.x;     // split
    const int t0   = s * CHUNK;

    // --- stage w_e into shared ---
    #pragma unroll
    for (int i = tid; i < HE; i += THREADS)
        we_sh[i] = attn_w[DEC + i];

    // --- h_b = hid_flat[b] . w_h + attn_b  (redundant per CTA; tiny, L2-hot) ---
    // hid_flat[b][d*1024+c] = hidden[d][b][c]
    float hp = 0.f;
    #pragma unroll
    for (int k = 0; k < DEC / THREADS; k++) {
        int idx = tid + k * THREADS;
        int d = idx >> 10, c = idx & 1023;
        hp += hidden[d * (NB * HE) + b * HE + c] * attn_w[idx];
    }
    red[tid] = hp;
    __syncthreads();
    for (int off = THREADS / 2; off > 0; off >>= 1) {
        if (tid < off) red[tid] += red[tid + off];
        __syncthreads();
    }
    if (tid == 0) {
        hb_sh = red[0] + attn_b[0];
        m_sh  = -1e30f;
        l_sh  = 0.f;
    }
    __syncthreads();
    const float hb = hb_sh;

    float4 acc = make_float4(0.f, 0.f, 0.f, 0.f);
    const float4* enc4 = (const float4*)(enc + (size_t)b * NT * HE);
    const float4* we4  = (const float4*)we_sh;

    for (int kt = 0; kt < NTILES; kt++) {
        const int tr = t0 + kt * TILE;

        // ---- load 8x1024 fp32 tile (32 KB) from HBM -> SMEM, float4, MLP=8 ----
        const float4* src = enc4 + (size_t)tr * (HE / 4);
        #pragma unroll
        for (int i = 0; i < (TILE * HE / 4) / THREADS; i++)
            tile[tid + i * THREADS] = src[tid + i * THREADS];
        __syncthreads();

        // ---- energies: warp w computes row w's dot with w_e ----
        float p = 0.f;
        #pragma unroll
        for (int j = 0; j < 8; j++) {
            float4 v = tile[wid * (HE / 4) + lane + 32 * j];
            float4 w = we4[lane + 32 * j];
            p += v.x * w.x + v.y * w.y + v.z * w.z + v.w * w.w;
        }
        #pragma unroll
        for (int o = 16; o > 0; o >>= 1)
            p += __shfl_xor_sync(0xffffffff, p, o);
        if (lane == 0) {
            float mv = mask[b * NT + tr + wid];
            e_sh[wid]    = mv * (p + hb);   // e1 = mask * raw_energy
            mask_sh[wid] = mv;
        }
        __syncthreads();

        // ---- online-softmax state update (thread 0) ----
        if (tid == 0) {
            float tm = e_sh[0];
            #pragma unroll
            for (int t = 1; t < TILE; t++) tm = fmaxf(tm, e_sh[t]);
            float nm = fmaxf(m_sh, tm);
            scale_sh = __expf(m_sh - nm);
            m_sh = nm;
        }
        __syncthreads();

        const float mcur = m_sh;
        if (tid < TILE)
            f_sh[tid] = mask_sh[tid] * __expf(e_sh[tid] - mcur);
        const float sc = scale_sh;
        acc.x *= sc; acc.y *= sc; acc.z *= sc; acc.w *= sc;
        __syncthreads();

        // ---- rank-1 accumulate from SMEM (thread owns 4 output cols) ----
        #pragma unroll
        for (int t = 0; t < TILE; t++) {
            float f  = f_sh[t];
            float4 v = tile[t * (HE / 4) + tid];
            acc.x += f * v.x; acc.y += f * v.y;
            acc.z += f * v.z; acc.w += f * v.w;
        }
        if (tid == 0) {
            float fs = 0.f;
            #pragma unroll
            for (int t = 0; t < TILE; t++) fs += f_sh[t];
            l_sh = l_sh * sc + fs;
        }
        __syncthreads();   // protect tile/e_sh/f_sh before next iteration
    }

    const int pidx = b * SPLITS + s;
    ((float4*)g_acc)[pidx * (HE / 4) + tid] = acc;
    if (tid == 0) { g_m[pidx] = m_sh; g_l[pidx] = l_sh; }
}

// ---------------------------------------------------------------------------
// Kernel 2: combine SPLITS partials per batch -> out[b][e]
// ---------------------------------------------------------------------------
__global__ __launch_bounds__(THREADS) void attn_combine_kernel(float* __restrict__ out)
{
    const int b   = blockIdx.x;
    const int tid = threadIdx.x;

    float M = -1e30f;
    #pragma unroll
    for (int s = 0; s < SPLITS; s++)
        M = fmaxf(M, g_m[b * SPLITS + s]);

    float  L = 0.f;
    float4 a = make_float4(0.f, 0.f, 0.f, 0.f);
    #pragma unroll
    for (int s = 0; s < SPLITS; s++) {
        const int pidx = b * SPLITS + s;
        float w = __expf(g_m[pidx] - M);
        L += w * g_l[pidx];
        float4 v = ((const float4*)g_acc)[pidx * (HE / 4) + tid];
        a.x += w * v.x; a.y += w * v.y; a.z += w * v.z; a.w += w * v.w;
    }
    const float inv = 1.f / L;
    ((float4*)out)[b * (HE / 4) + tid] =
        make_float4(a.x * inv, a.y * inv, a.z * inv, a.w * inv);
}

// ---------------------------------------------------------------------------
// Launch
// ---------------------------------------------------------------------------
extern "C" void kernel_launch(void* const* d_in, const int* in_sizes, int n_in,
                              void* d_out, int out_size)
{
    const float* hidden = (const float*)d_in[0];   // (2, 32, 1024)
    const float* enc    = (const float*)d_in[1];   // (32, 2048, 1024)
    const float* mask   = (const float*)d_in[2];   // (32, 2048)
    const float* attn_w = (const float*)d_in[3];   // (3072,)
    const float* attn_b = (const float*)d_in[4];   // (1,)
    float* out = (float*)d_out;                    // (32, 1024)

    dim3 grid1(SPLITS, NB);
    attn_partial_kernel<<<grid1, THREADS>>>(hidden, enc, mask, attn_w, attn_b);
    attn_combine_kernel<<<NB, THREADS>>>(out);
}

// round 5
// speedup vs baseline: 1.1466x; 1.1466x over previous
#include <cuda_runtime.h>

// Problem constants (fixed by the reference shapes)
#define NB      32          // batch
#define NT      2048        // encoder time steps
#define HE      1024        // encoder hidden
#define DEC     2048        // flattened decoder hidden (2*1024)

#define SPLITS  16          // T-splits per batch
#define CHUNK   (NT / SPLITS)       // 128 rows per CTA
#define TILE    4                   // rows per register tile
#define NTILES  (CHUNK / TILE)      // 32
#define THREADS 256

// Split partials: 32*16*1024 fp32 acc + m + l  (~2 MB static device scratch)
__device__ float g_acc[NB * SPLITS * HE];
__device__ float g_m[NB * SPLITS];
__device__ float g_l[NB * SPLITS];

// ---------------------------------------------------------------------------
// Kernel 1: per-(batch, split) flash-style single-query attention partial.
// Fully register-resident data path: thread tid owns float4 column tid of
// every row. Each enc element is loaded from HBM exactly once and used twice
// (energy dot + weighted accumulate) from registers. Only the per-row energy
// reduction crosses threads -> ONE barrier per 4-row tile (double-buffered
// reduction scratch removes the second barrier).
// ---------------------------------------------------------------------------
__global__ __launch_bounds__(THREADS, 4) void attn_partial_kernel(
    const float* __restrict__ hidden,   // (2, 32, 1024)
    const float* __restrict__ enc,      // (32, 2048, 1024)
    const float* __restrict__ mask,     // (32, 2048)
    const float* __restrict__ attn_w,   // (3072,)
    const float* __restrict__ attn_b)   // (1,)
{
    __shared__ float red[2][TILE][8];    // [buf][row][warp] partial sums
    __shared__ float msh[2][TILE];       // [buf][row] mask values
    __shared__ float hred[THREADS];

    const int tid  = threadIdx.x;
    const int lane = tid & 31;
    const int wid  = tid >> 5;
    const int b    = blockIdx.y;
    const int s    = blockIdx.x;
    const int t0   = s * CHUNK;

    // --- h_b = hid_flat[b] . w_h + attn_b (block reduction, done once) ---
    float hp = 0.f;
    #pragma unroll
    for (int k = 0; k < DEC / THREADS; k++) {
        int idx = tid + k * THREADS;
        int d = idx >> 10, c = idx & 1023;
        hp += hidden[d * (NB * HE) + b * HE + c] * attn_w[idx];
    }
    hred[tid] = hp;
    __syncthreads();
    for (int off = THREADS / 2; off > 0; off >>= 1) {
        if (tid < off) hred[tid] += hred[tid + off];
        __syncthreads();
    }
    const float hb = hred[0] + attn_b[0];

    // w_e slice for this thread's column (register resident)
    const float4 we = ((const float4*)(attn_w + DEC))[tid];

    const float4* encb = (const float4*)(enc + (size_t)b * NT * HE);
    float4 acc = make_float4(0.f, 0.f, 0.f, 0.f);
    float  m   = -1e30f;
    float  l   = 0.f;

    for (int kt = 0; kt < NTILES; kt++) {
        const int tr  = t0 + kt * TILE;
        const int buf = kt & 1;

        // ---- 4 independent LDG.128, front-batched (MLP=4/thread) ----
        float4 v[TILE];
        #pragma unroll
        for (int i = 0; i < TILE; i++)
            v[i] = encb[(size_t)(tr + i) * (HE / 4) + tid];

        // ---- per-thread energy partials, warp butterfly reduce ----
        float p[TILE];
        #pragma unroll
        for (int i = 0; i < TILE; i++)
            p[i] = v[i].x * we.x + v[i].y * we.y + v[i].z * we.z + v[i].w * we.w;
        #pragma unroll
        for (int o = 16; o > 0; o >>= 1) {
            #pragma unroll
            for (int i = 0; i < TILE; i++)
                p[i] += __shfl_xor_sync(0xffffffffu, p[i], o);
        }
        if (lane == 0) {
            #pragma unroll
            for (int i = 0; i < TILE; i++)
                red[buf][i][wid] = p[i];
        }
        if (tid < TILE)
            msh[buf][tid] = mask[b * NT + tr + tid];
        __syncthreads();   // the ONLY barrier in the tile loop

        // ---- all threads redundantly: cross-warp sum, online softmax ----
        float e[TILE], mk[TILE];
        float tm = -1e30f;
        #pragma unroll
        for (int i = 0; i < TILE; i++) {
            float sum = 0.f;
            #pragma unroll
            for (int w = 0; w < 8; w++) sum += red[buf][i][w];
            mk[i] = msh[buf][i];
            e[i]  = mk[i] * (sum + hb);
            tm = fmaxf(tm, e[i]);
        }
        const float nm = fmaxf(m, tm);
        const float sc = __expf(m - nm);
        m = nm;

        float f[TILE];
        float fs = 0.f;
        #pragma unroll
        for (int i = 0; i < TILE; i++) {
            f[i] = mk[i] * __expf(e[i] - nm);
            fs += f[i];
        }
        l = l * sc + fs;
        acc.x *= sc; acc.y *= sc; acc.z *= sc; acc.w *= sc;

        // ---- rank-1 accumulate straight from registers ----
        #pragma unroll
        for (int i = 0; i < TILE; i++) {
            acc.x += f[i] * v[i].x; acc.y += f[i] * v[i].y;
            acc.z += f[i] * v[i].z; acc.w += f[i] * v[i].w;
        }
    }

    const int pidx = b * SPLITS + s;
    ((float4*)g_acc)[pidx * (HE / 4) + tid] = acc;
    if (tid == 0) { g_m[pidx] = m; g_l[pidx] = l; }
}

// ---------------------------------------------------------------------------
// Kernel 2: combine SPLITS partials per batch -> out[b][e]
// 128 CTAs (4 column-quarters x 32 batches); 4-way split-group reduction.
// ---------------------------------------------------------------------------
__global__ __launch_bounds__(THREADS) void attn_combine_kernel(float* __restrict__ out)
{
    __shared__ float4 sm[4][64];

    const int b   = blockIdx.y;
    const int q   = blockIdx.x;      // column quarter 0..3
    const int tid = threadIdx.x;
    const int sg  = tid >> 6;        // split group 0..3
    const int c   = tid & 63;
    const int col = q * 64 + c;      // float4 column 0..255

    float M = -1e30f;
    #pragma unroll
    for (int s2 = 0; s2 < SPLITS; s2++)
        M = fmaxf(M, g_m[b * SPLITS + s2]);
    float L = 0.f;
    #pragma unroll
    for (int s2 = 0; s2 < SPLITS; s2++)
        L += __expf(g_m[b * SPLITS + s2] - M) * g_l[b * SPLITS + s2];

    float4 a = make_float4(0.f, 0.f, 0.f, 0.f);
    #pragma unroll
    for (int j = 0; j < 4; j++) {
        const int pidx = b * SPLITS + (sg + j * 4);
        const float w = __expf(g_m[pidx] - M);
        const float4 v = ((const float4*)g_acc)[pidx * (HE / 4) + col];
        a.x += w * v.x; a.y += w * v.y; a.z += w * v.z; a.w += w * v.w;
    }
    sm[sg][c] = a;
    __syncthreads();

    if (sg == 0) {
        const float4 r0 = sm[0][c], r1 = sm[1][c], r2 = sm[2][c], r3 = sm[3][c];
        const float inv = 1.f / L;
        ((float4*)out)[b * (HE / 4) + col] = make_float4(
            (r0.x + r1.x + r2.x + r3.x) * inv,
            (r0.y + r1.y + r2.y + r3.y) * inv,
            (r0.z + r1.z + r2.z + r3.z) * inv,
            (r0.w + r1.w + r2.w + r3.w) * inv);
    }
}

// ---------------------------------------------------------------------------
// Launch
// ---------------------------------------------------------------------------
extern "C" void kernel_launch(void* const* d_in, const int* in_sizes, int n_in,
                              void* d_out, int out_size)
{
    const float* hidden = (const float*)d_in[0];   // (2, 32, 1024)
    const float* enc    = (const float*)d_in[1];   // (32, 2048, 1024)
    const float* mask   = (const float*)d_in[2];   // (32, 2048)
    const float* attn_w = (const float*)d_in[3];   // (3072,)
    const float* attn_b = (const float*)d_in[4];   // (1,)
    float* out = (float*)d_out;                    // (32, 1024)

    dim3 grid1(SPLITS, NB);
    attn_partial_kernel<<<grid1, THREADS>>>(hidden, enc, mask, attn_w, attn_b);
    dim3 grid2(4, NB);
    attn_combine_kernel<<<grid2, THREADS>>>(out);
}

// round 7
// speedup vs baseline: 1.1771x; 1.0266x over previous
#include <cuda_runtime.h>

// Problem constants (fixed by the reference shapes)
#define NB      32          // batch
#define NT      2048        // encoder time steps
#define HE      1024        // encoder hidden
#define DEC     2048        // flattened decoder hidden (2*1024)

#define SPLITS  16          // T-splits per batch
#define CHUNK   (NT / SPLITS)       // 128 rows per CTA
#define TILE    2                   // rows per register tile (double-buffered)
#define NTILES  (CHUNK / TILE)      // 64
#define THREADS 256

// Split partials: 32*16*1024 fp32 acc + m + l  (~2 MB static device scratch)
__device__ float g_acc[NB * SPLITS * HE];
__device__ float g_m[NB * SPLITS];
__device__ float g_l[NB * SPLITS];
__device__ unsigned int g_cnt[NB];   // zero-initialized; self-resetting

// ---------------------------------------------------------------------------
// Per-(batch, split) flash-style single-query attention partial, with the
// split-combine fused into the last-arriving CTA per batch.
//
// Data path is register-resident: thread tid owns float4 column tid of every
// row; each enc element is loaded from HBM once and used twice from registers.
// The tile loop is software-pipelined: tile kt+1's LDG.128s are issued before
// tile kt is consumed, so loads stay in flight across the shuffle-reduce,
// barrier and accumulate phases (HBM duty cycle ~100%).
// ---------------------------------------------------------------------------
__global__ __launch_bounds__(THREADS, 4) void attn_partial_kernel(
    const float* __restrict__ hidden,   // (2, 32, 1024)
    const float* __restrict__ enc,      // (32, 2048, 1024)
    const float* __restrict__ mask,     // (32, 2048)
    const float* __restrict__ attn_w,   // (3072,)
    const float* __restrict__ attn_b,   // (1,)
    float* __restrict__ out)            // (32, 1024)
{
    __shared__ float red[2][TILE][8];    // [buf][row][warp] energy partials
    __shared__ float msk_all[CHUNK];     // this chunk's mask values
    __shared__ float hred[THREADS];
    __shared__ unsigned int done_sh;

    const int tid  = threadIdx.x;
    const int lane = tid & 31;
    const int wid  = tid >> 5;
    const int b    = blockIdx.y;
    const int s    = blockIdx.x;
    const int t0   = s * CHUNK;

    // --- stage this chunk's mask (512 B) once ---
    if (tid < CHUNK)
        msk_all[tid] = mask[b * NT + t0 + tid];

    // --- h_b = hid_flat[b] . w_h + attn_b (block reduction, done once) ---
    float hp = 0.f;
    #pragma unroll
    for (int k = 0; k < DEC / THREADS; k++) {
        int idx = tid + k * THREADS;
        int d = idx >> 10, c = idx & 1023;
        hp += hidden[d * (NB * HE) + b * HE + c] * attn_w[idx];
    }
    hred[tid] = hp;
    __syncthreads();
    for (int off = THREADS / 2; off > 0; off >>= 1) {
        if (tid < off) hred[tid] += hred[tid + off];
        __syncthreads();
    }
    const float hb = hred[0] + attn_b[0];

    // w_e slice for this thread's column (register resident)
    const float4 we = ((const float4*)(attn_w + DEC))[tid];

    const float4* encb = (const float4*)(enc + (size_t)b * NT * HE);
    float4 acc = make_float4(0.f, 0.f, 0.f, 0.f);
    float  m   = -1e30f;
    float  l   = 0.f;

    // ---- software-pipelined tile loop ----
    float4 v[2][TILE];
    #pragma unroll
    for (int i = 0; i < TILE; i++)
        v[0][i] = encb[(size_t)(t0 + i) * (HE / 4) + tid];

    #pragma unroll 2
    for (int kt = 0; kt < NTILES; kt++) {
        const int cur = kt & 1;
        const int tr  = kt * TILE;        // row offset within chunk

        // prefetch next tile (stays in flight through everything below)
        if (kt + 1 < NTILES) {
            #pragma unroll
            for (int i = 0; i < TILE; i++)
                v[cur ^ 1][i] = encb[(size_t)(t0 + tr + TILE + i) * (HE / 4) + tid];
        }

        // per-thread energy partials, warp butterfly reduce (rows independent)
        float p[TILE];
        #pragma unroll
        for (int i = 0; i < TILE; i++)
            p[i] = v[cur][i].x * we.x + v[cur][i].y * we.y
                 + v[cur][i].z * we.z + v[cur][i].w * we.w;
        #pragma unroll
        for (int o = 16; o > 0; o >>= 1) {
            #pragma unroll
            for (int i = 0; i < TILE; i++)
                p[i] += __shfl_xor_sync(0xffffffffu, p[i], o);
        }
        if (lane == 0) {
            #pragma unroll
            for (int i = 0; i < TILE; i++)
                red[cur][i][wid] = p[i];
        }
        __syncthreads();   // the only per-tile barrier

        // all threads redundantly: cross-warp sum + online softmax update
        float e[TILE], mk[TILE];
        float tm = -1e30f;
        #pragma unroll
        for (int i = 0; i < TILE; i++) {
            float sum = 0.f;
            #pragma unroll
            for (int w = 0; w < 8; w++) sum += red[cur][i][w];
            mk[i] = msk_all[tr + i];
            e[i]  = mk[i] * (sum + hb);
            tm = fmaxf(tm, e[i]);
        }
        const float nm = fmaxf(m, tm);
        const float sc = __expf(m - nm);
        m = nm;

        float f[TILE];
        float fs = 0.f;
        #pragma unroll
        for (int i = 0; i < TILE; i++) {
            f[i] = mk[i] * __expf(e[i] - nm);
            fs += f[i];
        }
        l = l * sc + fs;
        acc.x *= sc; acc.y *= sc; acc.z *= sc; acc.w *= sc;

        // rank-1 accumulate straight from registers
        #pragma unroll
        for (int i = 0; i < TILE; i++) {
            acc.x += f[i] * v[cur][i].x; acc.y += f[i] * v[cur][i].y;
            acc.z += f[i] * v[cur][i].z; acc.w += f[i] * v[cur][i].w;
        }
    }

    // ---- publish this split's partial ----
    const int pidx = b * SPLITS + s;
    ((float4*)g_acc)[pidx * (HE / 4) + tid] = acc;
    if (tid == 0) { g_m[pidx] = m; g_l[pidx] = l; }

    // ---- last CTA of this batch performs the combine (fence+atomic) ----
    __threadfence();
    if (tid == 0)
        done_sh = atomicAdd(&g_cnt[b], 1u);
    __syncthreads();
    if (done_sh == SPLITS - 1) {
        __threadfence();                 // acquire: see all partials
        if (tid == 0) g_cnt[b] = 0;      // reset for next graph replay

        float M = -1e30f;
        #pragma unroll
        for (int s2 = 0; s2 < SPLITS; s2++)
            M = fmaxf(M, g_m[b * SPLITS + s2]);

        float  L = 0.f;
        float4 a = make_float4(0.f, 0.f, 0.f, 0.f);
        #pragma unroll
        for (int s2 = 0; s2 < SPLITS; s2++) {
            const int pj = b * SPLITS + s2;
            const float w = __expf(g_m[pj] - M);
            L += w * g_l[pj];
            const float4 pv = ((const float4*)g_acc)[pj * (HE / 4) + tid];
            a.x += w * pv.x; a.y += w * pv.y; a.z += w * pv.z; a.w += w * pv.w;
        }
        const float inv = 1.f / L;
        ((float4*)out)[b * (HE / 4) + tid] =
            make_float4(a.x * inv, a.y * inv, a.z * inv, a.w * inv);
    }
}

// ---------------------------------------------------------------------------
// Launch: single fused kernel
// ---------------------------------------------------------------------------
extern "C" void kernel_launch(void* const* d_in, const int* in_sizes, int n_in,
                              void* d_out, int out_size)
{
    const float* hidden = (const float*)d_in[0];   // (2, 32, 1024)
    const float* enc    = (const float*)d_in[1];   // (32, 2048, 1024)
    const float* mask   = (const float*)d_in[2];   // (32, 2048)
    const float* attn_w = (const float*)d_in[3];   // (3072,)
    const float* attn_b = (const float*)d_in[4];   // (1,)
    float* out = (float*)d_out;                    // (32, 1024)

    dim3 grid(SPLITS, NB);
    attn_partial_kernel<<<grid, THREADS>>>(hidden, enc, mask, attn_w, attn_b, out);
}

// round 10
// speedup vs baseline: 1.3105x; 1.1134x over previous
#include <cuda_runtime.h>

// Problem constants (fixed by the reference shapes)
#define NB      32          // batch
#define NT      2048        // encoder time steps
#define HE      1024        // encoder hidden
#define DEC     2048        // flattened decoder hidden (2*1024)

#define SPLITS  16          // T-splits per batch
#define CHUNK   (NT / SPLITS)   // 128 rows per CTA
#define NGROUP  2               // independent 128-thread groups per CTA
#define GROWS   (CHUNK / NGROUP) // 64 rows per group
#define THREADS 256

// Split partials: 32*16*1024 fp32 acc + m + l  (~2 MB static device scratch)
__device__ float g_acc[NB * SPLITS * HE];
__device__ float g_m[NB * SPLITS];
__device__ float g_l[NB * SPLITS];
__device__ unsigned int g_cnt[NB];   // zero-initialized; self-resetting

// ---------------------------------------------------------------------------
// Flash-style single-query attention. Each CTA = 2 INDEPENDENT 128-thread
// groups (named-barrier synced, 4 warps each) so warps never convoy on a
// CTA-wide barrier: groups drift, load issue de-bunches, HBM stays fed.
// Thread owns float4 columns {idx128, idx128+128} of every row; each enc
// element is loaded once and used twice from registers.
// ---------------------------------------------------------------------------
__global__ __launch_bounds__(THREADS, 4) void attn_partial_kernel(
    const float* __restrict__ hidden,   // (2, 32, 1024)
    const float* __restrict__ enc,      // (32, 2048, 1024)
    const float* __restrict__ mask,     // (32, 2048)
    const float* __restrict__ attn_w,   // (3072,)
    const float* __restrict__ attn_b,   // (1,)
    float* __restrict__ out)            // (32, 1024)
{
    __shared__ float  msk[CHUNK];            // chunk mask values (512 B)
    __shared__ float  hred[THREADS];
    __shared__ float  ered[NGROUP][2][4];    // [group][buf][warp-in-group]
    __shared__ float  gm[NGROUP], gl[NGROUP];
    __shared__ float4 sacc[NGROUP][128][2];  // group accumulators (8 KB)
    __shared__ unsigned int done_sh;

    const int tid    = threadIdx.x;
    const int lane   = tid & 31;
    const int g      = tid >> 7;         // group 0/1
    const int idx128 = tid & 127;        // thread-in-group
    const int w4     = (tid >> 5) & 3;   // warp-in-group
    const int b      = blockIdx.y;
    const int s      = blockIdx.x;
    const int t0     = s * CHUNK;

    // --- stage chunk mask once ---
    if (tid < CHUNK)
        msk[tid] = mask[b * NT + t0 + tid];

    // --- h_b = hid_flat[b] . w_h + attn_b (CTA reduction, once) ---
    float hp = 0.f;
    #pragma unroll
    for (int k = 0; k < DEC / THREADS; k++) {
        int idx = tid + k * THREADS;
        int d = idx >> 10, c = idx & 1023;
        hp += hidden[d * (NB * HE) + b * HE + c] * attn_w[idx];
    }
    hred[tid] = hp;
    __syncthreads();
    for (int off = THREADS / 2; off > 0; off >>= 1) {
        if (tid < off) hred[tid] += hred[tid + off];
        __syncthreads();
    }
    const float hb = hred[0] + attn_b[0];

    // w_e slice for this thread's two float4 columns (register resident)
    const float4 we0 = ((const float4*)(attn_w + DEC))[idx128];
    const float4 we1 = ((const float4*)(attn_w + DEC))[idx128 + 128];

    // group's row pointer: rows [g*GROWS, (g+1)*GROWS) of the chunk
    const float4* p = (const float4*)(enc + (size_t)b * NT * HE)
                    + (size_t)(t0 + g * GROWS) * (HE / 4) + idx128;

    float4 acc0 = make_float4(0.f, 0.f, 0.f, 0.f);
    float4 acc1 = make_float4(0.f, 0.f, 0.f, 0.f);
    float  m = -1e30f, l = 0.f;

    // preload row 0
    float4 v0 = p[0], v1 = p[128];
    p += HE / 4;

    #pragma unroll 2
    for (int r = 0; r < GROWS; r++) {
        // prefetch next row (in flight through the whole chain below)
        float4 n0, n1;
        if (r + 1 < GROWS) { n0 = p[0]; n1 = p[128]; p += HE / 4; }

        // energy partial + intra-warp reduce
        float pe = v0.x * we0.x + v0.y * we0.y + v0.z * we0.z + v0.w * we0.w
                 + v1.x * we1.x + v1.y * we1.y + v1.z * we1.z + v1.w * we1.w;
        #pragma unroll
        for (int o = 16; o > 0; o >>= 1)
            pe += __shfl_xor_sync(0xffffffffu, pe, o);

        const int buf = r & 1;
        if (lane == 0)
            ered[g][buf][w4] = pe;
        // group-local barrier: couples only 4 warps, ids 1/2
        asm volatile("bar.sync %0, %1;" :: "r"(g + 1), "r"(128) : "memory");

        const float sum = ered[g][buf][0] + ered[g][buf][1]
                        + ered[g][buf][2] + ered[g][buf][3];
        const float mk = msk[g * GROWS + r];
        const float e  = mk * (sum + hb);
        const float nm = fmaxf(m, e);
        const float sc = __expf(m - nm);
        const float f  = mk * __expf(e - nm);
        m = nm;
        l = l * sc + f;

        acc0.x = acc0.x * sc + f * v0.x;  acc0.y = acc0.y * sc + f * v0.y;
        acc0.z = acc0.z * sc + f * v0.z;  acc0.w = acc0.w * sc + f * v0.w;
        acc1.x = acc1.x * sc + f * v1.x;  acc1.y = acc1.y * sc + f * v1.y;
        acc1.z = acc1.z * sc + f * v1.z;  acc1.w = acc1.w * sc + f * v1.w;

        v0 = n0; v1 = n1;
    }

    // ---- intra-CTA combine of the 2 group partials ----
    sacc[g][idx128][0] = acc0;
    sacc[g][idx128][1] = acc1;
    if (idx128 == 0) { gm[g] = m; gl[g] = l; }
    __syncthreads();

    const float M  = fmaxf(gm[0], gm[1]);
    const float w0 = __expf(gm[0] - M);
    const float w1 = __expf(gm[1] - M);
    const float L  = w0 * gl[0] + w1 * gl[1];

    const int pidx = b * SPLITS + s;
    {
        // thread t publishes float4 column t
        const int ci = tid & 127, cj = tid >> 7;
        const float4 a0 = sacc[0][ci][cj];
        const float4 a1 = sacc[1][ci][cj];
        float4 a;
        a.x = w0 * a0.x + w1 * a1.x;  a.y = w0 * a0.y + w1 * a1.y;
        a.z = w0 * a0.z + w1 * a1.z;  a.w = w0 * a0.w + w1 * a1.w;
        ((float4*)g_acc)[pidx * (HE / 4) + tid] = a;
    }
    if (tid == 0) { g_m[pidx] = M; g_l[pidx] = L; }

    // ---- last CTA of this batch combines the 16 splits ----
    __threadfence();
    if (tid == 0)
        done_sh = atomicAdd(&g_cnt[b], 1u);
    __syncthreads();
    if (done_sh == SPLITS - 1) {
        __threadfence();                 // acquire: see all partials
        if (tid == 0) g_cnt[b] = 0;      // reset for next graph replay

        float MM = -1e30f;
        #pragma unroll
        for (int s2 = 0; s2 < SPLITS; s2++)
            MM = fmaxf(MM, g_m[b * SPLITS + s2]);

        float  LL = 0.f;
        float4 a = make_float4(0.f, 0.f, 0.f, 0.f);
        #pragma unroll
        for (int s2 = 0; s2 < SPLITS; s2++) {
            const int pj = b * SPLITS + s2;
            const float w = __expf(g_m[pj] - MM);
            LL += w * g_l[pj];
            const float4 pv = ((const float4*)g_acc)[pj * (HE / 4) + tid];
            a.x += w * pv.x; a.y += w * pv.y; a.z += w * pv.z; a.w += w * pv.w;
        }
        const float inv = 1.f / LL;
        ((float4*)out)[b * (HE / 4) + tid] =
            make_float4(a.x * inv, a.y * inv, a.z * inv, a.w * inv);
    }
}

// ---------------------------------------------------------------------------
// Launch: single fused kernel
// ---------------------------------------------------------------------------
extern "C" void kernel_launch(void* const* d_in, const int* in_sizes, int n_in,
                              void* d_out, int out_size)
{
    const float* hidden = (const float*)d_in[0];   // (2, 32, 1024)
    const float* enc    = (const float*)d_in[1];   // (32, 2048, 1024)
    const float* mask   = (const float*)d_in[2];   // (32, 2048)
    const float* attn_w = (const float*)d_in[3];   // (3072,)
    const float* attn_b = (const float*)d_in[4];   // (1,)
    float* out = (float*)d_out;                    // (32, 1024)

    dim3 grid(SPLITS, NB);
    attn_partial_kernel<<<grid, THREADS>>>(hidden, enc, mask, attn_w, attn_b, out);
}